// round 6
// baseline (speedup 1.0000x reference)
#include <cuda_runtime.h>
#include <math_constants.h>
#include <math.h>

#define E 4
#define L 8
#define S 512
#define F 32
#define SAMPLE 512
#define ELF (E * L * F)      /* 1024 */

// ---------------- scratch (no allocations allowed) ----------------
__device__ float g_projT[ELF * S];            // [e][l][g][s]  raw proj (pre-std-scale)
__device__ float g_red[ELF * SAMPLE];         // kernel sums per (row, grid point)
__device__ float g_sp1[256 * F];              // per-(el,stile,f) partial sum
__device__ float g_sp2[256 * F];              // per-(el,stile,f) partial sumsq
__device__ float g_bmin[256], g_bmax[256];
__device__ float g_c[8];                      // 0:uscale 1:qleft 2:qstep 3:scale_out
__device__ float g_store[6 * L * F];          // per-pair summed |diff|

__device__ __forceinline__ float ex2(float x) {
    float y; asm("ex2.approx.ftz.f32 %0, %1;" : "=f"(y) : "f"(x)); return y;
}

// ---------------- K1: proj = matrix @ params + std partials + min/max ----------------
__global__ void __launch_bounds__(256) k_proj(const float* __restrict__ matrix,
                                              const float* __restrict__ params) {
    __shared__ float sp[F * F];
    __shared__ float mt[64 * F];
    __shared__ float rmin[256], rmax[256];
    __shared__ float ssum[256], ssq[256];
    int b = blockIdx.x;                 // el*8 + stile
    int stile = b & 7;
    int el = b >> 3;
    int tid = threadIdx.x;
    for (int k = tid; k < F * F; k += 256) sp[k] = params[k];
    const float* mbase = matrix + ((size_t)el * S + (size_t)stile * 64) * F;
    for (int k = tid; k < 64 * F; k += 256) mt[k] = mbase[k];
    __syncthreads();

    // std partials: f = tid&31, rowgroup = tid>>5 (8 groups over 64 rows)
    {
        int f2 = tid & 31, rg = tid >> 5;
        float s1 = 0.f, s2 = 0.f;
        #pragma unroll
        for (int r = rg; r < 64; r += 8) {
            float x = mt[r * F + f2];
            s1 += x; s2 += x * x;
        }
        ssum[tid] = s1; ssq[tid] = s2;
    }

    // projection + min/max
    float mn = CUDART_INF_F, mx = -CUDART_INF_F;
    int g = tid & 31;
    int sl0 = tid >> 5;
    #pragma unroll
    for (int k = 0; k < 8; k++) {
        int sl = sl0 + k * 8;
        float acc = 0.f;
        #pragma unroll
        for (int f = 0; f < F; f++)
            acc += mt[sl * F + f] * sp[f * F + g];
        g_projT[((size_t)el * F + g) * S + (size_t)stile * 64 + sl] = acc;
        mn = fminf(mn, acc); mx = fmaxf(mx, acc);
    }
    rmin[tid] = mn; rmax[tid] = mx;
    __syncthreads();
    for (int st = 128; st; st >>= 1) {
        if (tid < st) {
            rmin[tid] = fminf(rmin[tid], rmin[tid + st]);
            rmax[tid] = fmaxf(rmax[tid], rmax[tid + st]);
            if (st >= 32) { ssum[tid] += ssum[tid + st]; ssq[tid] += ssq[tid + st]; }
        }
        __syncthreads();
    }
    if (tid < 32) { g_sp1[b * 32 + tid] = ssum[tid]; g_sp2[b * 32 + tid] = ssq[tid]; }
    if (tid == 0) { g_bmin[b] = rmin[0]; g_bmax[b] = rmax[0]; }
}

// ---------------- K2: finalize scalars ----------------
__global__ void k_consts() {
    __shared__ float ssd[256], smn[256], smx[256];
    int t = threadIdx.x;   // 256 threads
    float sdsum = 0.f;
    for (int c = t; c < ELF; c += 256) {
        int el = c >> 5, f = c & 31;
        float s1 = 0.f, s2 = 0.f;
        #pragma unroll
        for (int st = 0; st < 8; st++) {
            int idx = ((el * 8 + st) << 5) + f;
            s1 += g_sp1[idx]; s2 += g_sp2[idx];
        }
        float mean = s1 / (float)S;
        float var = (s2 - s1 * mean) / (float)(S - 1);
        sdsum += sqrtf(fmaxf(var, 0.f));
    }
    ssd[t] = sdsum; smn[t] = g_bmin[t]; smx[t] = g_bmax[t];
    __syncthreads();
    for (int st = 128; st; st >>= 1) {
        if (t < st) {
            ssd[t] += ssd[t + st];
            smn[t] = fminf(smn[t], smn[t + st]);
            smx[t] = fmaxf(smx[t], smx[t + st]);
        }
        __syncthreads();
    }
    if (t == 0) {
        float stdv = ssd[0] / (float)ELF;
        // mean(std(matrix/stdv)) == stdv/stdv == 1 exactly (positive homogeneity)
        float bw = 1.06f * powf((float)S, -0.2f);
        float left = smn[0] / stdv, right = smx[0] / stdv;
        float range = right - left;
        float delta = range / (float)SAMPLE;
        float gstep = range / (float)(SAMPLE - 1);
        float inv2bw2 = 0.5f / (bw * bw);
        float coef = inv2bw2 * 1.4426950408889634f;  // exp(-a x^2) = 2^(-(x*sa)^2)
        float sa = sqrtf(coef);
        g_c[0] = sa / stdv;      // uscale
        g_c[1] = left * sa;      // qleft (scaled)
        g_c[2] = gstep * sa;     // qstep (scaled)
        float divisor = sqrtf(2.f * CUDART_PI_F) * bw;
        g_c[3] = delta / (2.f * divisor);   // final per-pair scale
    }
}

// ---------------- K3: hot KDE (windowed, sorted samples) ----------------
// masked-tail identity: (ksum - corr)/len == sum_{s<len} K(x_s - p)/len.
// terms with (scaled d)^2 > 27 are < 7.5e-9 -> dropped (window halfwidth sqrt(27)).
__global__ void __launch_bounds__(256) k_kde(const int* __restrict__ data_len) {
    __shared__ float sv[S];
    int elf = blockIdx.x;               // row = (e,l,f)
    int el = elf >> 5;
    int tid = threadIdx.x;
    int len = data_len[el];
    float uscale = g_c[0], qleft = g_c[1], qstep = g_c[2];

    // load scaled samples, pad invalid with +INF (sorts to the end, never in window)
    for (int s = tid; s < S; s += 256)
        sv[s] = (s < len) ? g_projT[(size_t)elf * S + s] * uscale : CUDART_INF_F;
    __syncthreads();

    // bitonic sort 512 elements, 256 threads
    for (int k = 2; k <= S; k <<= 1) {
        for (int j = k >> 1; j > 0; j >>= 1) {
            int i = ((tid & ~(j - 1)) << 1) | (tid & (j - 1));
            int ixj = i | j;
            float a = sv[i], c = sv[ixj];
            if ((a > c) == ((i & k) == 0)) { sv[i] = c; sv[ixj] = a; }
            __syncthreads();
        }
    }

    const float w = 5.1961524f;  // sqrt(27)
    #pragma unroll
    for (int h = 0; h < 2; h++) {
        int pt = tid + h * 256;
        float q = qleft + (float)pt * qstep;
        float lo_v = q - w, hi_v = q + w;
        // lower_bound(lo_v): fixed 9-step search (uniform trip count, no divergence)
        int lo, hi;
        {
            int l = 0, r = S;
            #pragma unroll
            for (int it = 0; it < 9; it++) {
                int m = (l + r) >> 1;
                if (sv[m] < lo_v) l = m + 1; else r = m;
            }
            lo = l;
        }
        {
            int l = 0, r = S;
            #pragma unroll
            for (int it = 0; it < 9; it++) {
                int m = (l + r) >> 1;
                if (sv[m] <= hi_v) l = m + 1; else r = m;
            }
            hi = l;
        }
        float a = 0.f;
        #pragma unroll 4
        for (int i = lo; i < hi; i++) {
            float d = sv[i] - q;
            a += ex2(-d * d);
        }
        g_red[(size_t)elf * SAMPLE + pt] = a;
    }
}

// ---------------- K4: pairwise |diff| sums over grid ----------------
__global__ void __launch_bounds__(256) k_pair(const int* __restrict__ data_len) {
    __shared__ float sred[6][256];
    int b = blockIdx.x;                 // l*F + f
    int l = b >> 5;
    int f = b & 31;
    int tid = threadIdx.x;
    float local[6];
    #pragma unroll
    for (int p = 0; p < 6; p++) local[p] = 0.f;
    #pragma unroll
    for (int half = 0; half < 2; half++) {
        int pt = tid + half * 256;
        float r[E];
        #pragma unroll
        for (int e = 0; e < E; e++) {
            size_t idx = ((size_t)((e * L + l) * F + f)) * SAMPLE + pt;
            r[e] = g_red[idx] / (float)data_len[e * L + l];
        }
        int p = 0;
        #pragma unroll
        for (int i = 0; i < E; i++)
            #pragma unroll
            for (int j = i + 1; j < E; j++)
                local[p++] += fabsf(r[i] - r[j]);
    }
    #pragma unroll
    for (int p = 0; p < 6; p++) sred[p][tid] = local[p];
    __syncthreads();
    for (int st = 128; st; st >>= 1) {
        if (tid < st)
            #pragma unroll
            for (int p = 0; p < 6; p++) sred[p][tid] += sred[p][tid + st];
        __syncthreads();
    }
    if (tid < 6) g_store[tid * (L * F) + b] = sred[tid][0];
}

// ---------------- K5: maxima over pairs + scalars -> output ----------------
// pair order (i<j): 0:(0,1) 1:(0,2) 2:(0,3) 3:(1,2) 4:(1,3) 5:(2,3); train = {0,1,3}
__global__ void k_out(float* __restrict__ out) {
    __shared__ float str[256], ste[256];
    int tid = threadIdx.x;              // 256 = L*F
    float sc = g_c[3];
    float s0 = g_store[0 * 256 + tid], s1 = g_store[1 * 256 + tid], s2 = g_store[2 * 256 + tid];
    float s3 = g_store[3 * 256 + tid], s4 = g_store[4 * 256 + tid], s5 = g_store[5 * 256 + tid];
    float te = fmaxf(fmaxf(fmaxf(s0, s1), fmaxf(s2, s3)), fmaxf(s4, s5)) * sc;
    float tr = fmaxf(fmaxf(s0, s1), s3) * sc;
    out[tid] = tr;          // train_results (L,F)
    out[256 + tid] = te;    // test_results  (L,F)
    str[tid] = tr; ste[tid] = te;
    __syncthreads();
    if (tid < 32) {
        float mtr = -CUDART_INF_F, mte = -CUDART_INF_F;
        #pragma unroll
        for (int l = 0; l < L; l++) {
            mtr = fmaxf(mtr, str[l * 32 + tid]);
            mte = fmaxf(mte, ste[l * 32 + tid]);
        }
        #pragma unroll
        for (int o = 16; o; o >>= 1) {
            mtr += __shfl_down_sync(0xffffffffu, mtr, o);
            mte += __shfl_down_sync(0xffffffffu, mte, o);
        }
        if (tid == 0) { out[512] = mtr / 32.f; out[513] = mte / 32.f; }
    }
}

extern "C" void kernel_launch(void* const* d_in, const int* in_sizes, int n_in,
                              void* d_out, int out_size) {
    const float* matrix   = (const float*)d_in[0];   // (E,L,S,F) f32
    const float* params   = (const float*)d_in[1];   // (F,F) f32
    const int*   data_len = (const int*)d_in[2];     // (E,L) i32
    float* out = (float*)d_out;                      // 514 f32

    k_proj<<<256, 256>>>(matrix, params);
    k_consts<<<1, 256>>>();
    k_kde<<<ELF, 256>>>(data_len);
    k_pair<<<L * F, 256>>>(data_len);
    k_out<<<1, 256>>>(out);
}

// round 7
// speedup vs baseline: 1.2699x; 1.2699x over previous
#include <cuda_runtime.h>
#include <math_constants.h>
#include <math.h>

#define E 4
#define L 8
#define S 512
#define F 32
#define SAMPLE 512
#define ELF (E * L * F)      /* 1024 */

// ---------------- scratch (no allocations allowed) ----------------
__device__ float g_projT[ELF * S];            // [e][l][g][s]  raw proj (pre-std-scale)
__device__ float g_red[ELF * SAMPLE];         // red = ksum/len per (row, grid point)
__device__ float g_stdpart[E * L];
__device__ float g_bmin[256], g_bmax[256];
__device__ float g_c[8];                      // 0:uscale 1:qleft 2:qstep 3:scale_out
__device__ float g_store[6 * L * F];          // per-pair summed |diff|

__device__ __forceinline__ float ex2(float x) {
    float y; asm("ex2.approx.ftz.f32 %0, %1;" : "=f"(y) : "f"(x)); return y;
}
// f32x2 packed helpers (Blackwell packed fp32 pipe)
__device__ __forceinline__ unsigned long long pk2(float a, float b) {
    unsigned long long r; asm("mov.b64 %0, {%1, %2};" : "=l"(r) : "f"(a), "f"(b)); return r;
}
__device__ __forceinline__ void upk2(unsigned long long v, float& a, float& b) {
    asm("mov.b64 {%0, %1}, %2;" : "=f"(a), "=f"(b) : "l"(v));
}
__device__ __forceinline__ unsigned long long mul2(unsigned long long a, unsigned long long b) {
    unsigned long long r; asm("mul.rn.f32x2 %0, %1, %2;" : "=l"(r) : "l"(a), "l"(b)); return r;
}
__device__ __forceinline__ unsigned long long add2(unsigned long long a, unsigned long long b) {
    unsigned long long r; asm("add.rn.f32x2 %0, %1, %2;" : "=l"(r) : "l"(a), "l"(b)); return r;
}

// ---------------- K1: per-(e,l,f) std (ddof=1), partial sums ----------------
__global__ void k_std(const float* __restrict__ matrix) {
    __shared__ float ssum[256], ssq[256];
    int b = blockIdx.x;                 // e*L + l
    int tid = threadIdx.x;
    int f = tid & 31, sg = tid >> 5;    // 32 f x 8 s-groups
    const float* base = matrix + (size_t)b * S * F;
    float s1 = 0.f, s2 = 0.f;
    for (int s = sg; s < S; s += 8) {
        float x = base[s * F + f];
        s1 += x; s2 += x * x;
    }
    ssum[tid] = s1; ssq[tid] = s2;
    __syncthreads();
    for (int st = 128; st >= 32; st >>= 1) {
        if (tid < st) { ssum[tid] += ssum[tid + st]; ssq[tid] += ssq[tid + st]; }
        __syncthreads();
    }
    if (tid < 32) {
        float sum = ssum[tid], sq = ssq[tid];
        float mean = sum / (float)S;
        float var = (sq - sum * mean) / (float)(S - 1);
        float sd = sqrtf(fmaxf(var, 0.f));
        #pragma unroll
        for (int o = 16; o; o >>= 1) sd += __shfl_down_sync(0xffffffffu, sd, o);
        if (tid == 0) g_stdpart[b] = sd;
    }
}

// ---------------- K2: proj = matrix @ params (raw), transposed store + min/max ----------------
__global__ void __launch_bounds__(256) k_proj(const float* __restrict__ matrix,
                                              const float* __restrict__ params) {
    __shared__ float sp[F * F];
    __shared__ float mt[64 * F];
    __shared__ float rmin[256], rmax[256];
    int b = blockIdx.x;                 // el*8 + stile
    int stile = b & 7;
    int el = b >> 3;
    int tid = threadIdx.x;
    for (int k = tid; k < F * F; k += 256) sp[k] = params[k];
    const float* mbase = matrix + ((size_t)el * S + (size_t)stile * 64) * F;
    for (int k = tid; k < 64 * F; k += 256) mt[k] = mbase[k];
    __syncthreads();
    float mn = CUDART_INF_F, mx = -CUDART_INF_F;
    int g = tid & 31;
    int sl0 = tid >> 5;
    #pragma unroll
    for (int k = 0; k < 8; k++) {
        int sl = sl0 + k * 8;
        float acc = 0.f;
        #pragma unroll
        for (int f = 0; f < F; f++)
            acc += mt[sl * F + f] * sp[f * F + g];
        g_projT[((size_t)el * F + g) * S + (size_t)stile * 64 + sl] = acc;
        mn = fminf(mn, acc); mx = fmaxf(mx, acc);
    }
    rmin[tid] = mn; rmax[tid] = mx;
    __syncthreads();
    for (int st = 128; st; st >>= 1) {
        if (tid < st) {
            rmin[tid] = fminf(rmin[tid], rmin[tid + st]);
            rmax[tid] = fmaxf(rmax[tid], rmax[tid + st]);
        }
        __syncthreads();
    }
    if (tid == 0) { g_bmin[b] = rmin[0]; g_bmax[b] = rmax[0]; }
}

// ---------------- K3: finalize scalars ----------------
__global__ void k_consts() {
    int t = threadIdx.x;   // 32 threads
    float sd = (t < E * L) ? g_stdpart[t] : 0.f;
    #pragma unroll
    for (int o = 16; o; o >>= 1) sd += __shfl_down_sync(0xffffffffu, sd, o);
    sd = __shfl_sync(0xffffffffu, sd, 0);
    float mn = CUDART_INF_F, mx = -CUDART_INF_F;
    for (int i = t; i < 256; i += 32) {
        mn = fminf(mn, g_bmin[i]); mx = fmaxf(mx, g_bmax[i]);
    }
    #pragma unroll
    for (int o = 16; o; o >>= 1) {
        mn = fminf(mn, __shfl_down_sync(0xffffffffu, mn, o));
        mx = fmaxf(mx, __shfl_down_sync(0xffffffffu, mx, o));
    }
    if (t == 0) {
        float stdv = sd / (float)ELF;
        // mean(std(matrix/stdv)) == stdv/stdv == 1 exactly (positive homogeneity)
        float bw = 1.06f * powf((float)S, -0.2f);
        float left = mn / stdv, right = mx / stdv;
        float range = right - left;
        float delta = range / (float)SAMPLE;
        float gstep = range / (float)(SAMPLE - 1);
        float inv2bw2 = 0.5f / (bw * bw);
        float coef = inv2bw2 * 1.4426950408889634f;  // exp(-a x^2) = 2^(-(x*sa)^2)
        float sa = sqrtf(coef);
        g_c[0] = sa / stdv;      // uscale
        g_c[1] = left * sa;      // qleft (scaled)
        g_c[2] = gstep * sa;     // qstep h (scaled)
        float divisor = sqrtf(2.f * CUDART_PI_F) * bw;
        g_c[3] = delta / (2.f * divisor);   // final per-pair scale
    }
}

// ---------------- K4: hot KDE — factored geometric recurrence (EXACT) ----------------
// K(u,p) = 2^{-(t0 - dp h)^2} = c * g^dp * W_dp,  c=2^{-t0^2}, g=2^{2 t0 h}, W_dp=2^{-(dp h)^2}.
// W_dp is sample-independent -> per sample only 2 EX2s; per grid point one packed mul+add.
// Masked-tail identity: (ksum - corr)/len == sum_{s<len} K/len -> only sum s<len.
__global__ void __launch_bounds__(64) k_kde(const int* __restrict__ data_len) {
    __shared__ float su[2][S];
    int warp = threadIdx.x >> 5, lane = threadIdx.x & 31;
    int elf = (blockIdx.x << 1) | warp;       // warp = one (e,l,f) row
    int el = elf >> 5;
    int len = data_len[el];
    float uscale = g_c[0], qleft = g_c[1], h = g_c[2];
    const float* src = g_projT + (size_t)elf * S;
    for (int s = lane; s < len; s += 32) su[warp][s] = src[s] * uscale;
    __syncwarp();

    float twoh = 2.0f * h;
    float qb = qleft + (float)(lane << 4) * h;   // chunk base: 16 points per lane
    float m2hqb = -twoh * qb;
    unsigned long long a0, a1, a2, a3, a4, a5, a6, a7;
    a0 = a1 = a2 = a3 = a4 = a5 = a6 = a7 = pk2(0.f, 0.f);

    for (int s = 0; s < len; s++) {
        float u = su[warp][s];
        float t0 = u - qb;
        float c = ex2(__fmul_rn(t0, -t0));
        float g = ex2(fmaf(u, twoh, m2hqb));
        float g2 = g * g;
        float g4 = g2 * g2;
        float g8 = g4 * g4;
        unsigned long long gg = pk2(g2, g2);
        unsigned long long tA = pk2(c, c * g);           // points (0,1)
        unsigned long long tB = mul2(tA, pk2(g8, g8));   // points (8,9)
        a0 = add2(a0, tA); tA = mul2(tA, gg);
        a4 = add2(a4, tB); tB = mul2(tB, gg);
        a1 = add2(a1, tA); tA = mul2(tA, gg);
        a5 = add2(a5, tB); tB = mul2(tB, gg);
        a2 = add2(a2, tA); tA = mul2(tA, gg);
        a6 = add2(a6, tB); tB = mul2(tB, gg);
        a3 = add2(a3, tA);
        a7 = add2(a7, tB);
    }

    float res[16];
    upk2(a0, res[0], res[1]);   upk2(a1, res[2], res[3]);
    upk2(a2, res[4], res[5]);   upk2(a3, res[6], res[7]);
    upk2(a4, res[8], res[9]);   upk2(a5, res[10], res[11]);
    upk2(a6, res[12], res[13]); upk2(a7, res[14], res[15]);
    float invlen = 1.0f / (float)len;
    #pragma unroll
    for (int dp = 0; dp < 16; dp++) {
        float dh = (float)dp * h;
        res[dp] = res[dp] * ex2(__fmul_rn(dh, -dh)) * invlen;   // * W_dp / len
    }
    float4* dst = (float4*)(g_red + (size_t)elf * SAMPLE + (lane << 4));
    dst[0] = make_float4(res[0], res[1], res[2], res[3]);
    dst[1] = make_float4(res[4], res[5], res[6], res[7]);
    dst[2] = make_float4(res[8], res[9], res[10], res[11]);
    dst[3] = make_float4(res[12], res[13], res[14], res[15]);
}

// ---------------- K5: pairwise |diff| sums over grid (no division, 1 pt/thread) ----------------
__global__ void __launch_bounds__(512) k_pair() {
    __shared__ float sred[6][512];
    int b = blockIdx.x;                 // l*F + f
    int tid = threadIdx.x;              // grid point
    float r[E];
    #pragma unroll
    for (int e = 0; e < E; e++)
        r[e] = g_red[((size_t)(e * 256 + b)) * SAMPLE + tid];
    float local[6];
    int p = 0;
    #pragma unroll
    for (int i = 0; i < E; i++)
        #pragma unroll
        for (int j = i + 1; j < E; j++)
            local[p++] = fabsf(r[i] - r[j]);
    #pragma unroll
    for (p = 0; p < 6; p++) sred[p][tid] = local[p];
    __syncthreads();
    for (int st = 256; st; st >>= 1) {
        if (tid < st)
            #pragma unroll
            for (int q = 0; q < 6; q++) sred[q][tid] += sred[q][tid + st];
        __syncthreads();
    }
    if (tid < 6) g_store[tid * (L * F) + b] = sred[tid][0];
}

// ---------------- K6: maxima over pairs + scalars -> output ----------------
// pair order (i<j): 0:(0,1) 1:(0,2) 2:(0,3) 3:(1,2) 4:(1,3) 5:(2,3); train = {0,1,3}
__global__ void k_out(float* __restrict__ out) {
    __shared__ float str[256], ste[256];
    int tid = threadIdx.x;              // 256 = L*F
    float sc = g_c[3];
    float s0 = g_store[0 * 256 + tid], s1 = g_store[1 * 256 + tid], s2 = g_store[2 * 256 + tid];
    float s3 = g_store[3 * 256 + tid], s4 = g_store[4 * 256 + tid], s5 = g_store[5 * 256 + tid];
    float te = fmaxf(fmaxf(fmaxf(s0, s1), fmaxf(s2, s3)), fmaxf(s4, s5)) * sc;
    float tr = fmaxf(fmaxf(s0, s1), s3) * sc;
    out[tid] = tr;          // train_results (L,F)
    out[256 + tid] = te;    // test_results  (L,F)
    str[tid] = tr; ste[tid] = te;
    __syncthreads();
    if (tid < 32) {
        float mtr = -CUDART_INF_F, mte = -CUDART_INF_F;
        #pragma unroll
        for (int l = 0; l < L; l++) {
            mtr = fmaxf(mtr, str[l * 32 + tid]);
            mte = fmaxf(mte, ste[l * 32 + tid]);
        }
        #pragma unroll
        for (int o = 16; o; o >>= 1) {
            mtr += __shfl_down_sync(0xffffffffu, mtr, o);
            mte += __shfl_down_sync(0xffffffffu, mte, o);
        }
        if (tid == 0) { out[512] = mtr / 32.f; out[513] = mte / 32.f; }
    }
}

extern "C" void kernel_launch(void* const* d_in, const int* in_sizes, int n_in,
                              void* d_out, int out_size) {
    const float* matrix   = (const float*)d_in[0];   // (E,L,S,F) f32
    const float* params   = (const float*)d_in[1];   // (F,F) f32
    const int*   data_len = (const int*)d_in[2];     // (E,L) i32
    float* out = (float*)d_out;                      // 514 f32

    k_std<<<E * L, 256>>>(matrix);
    k_proj<<<256, 256>>>(matrix, params);
    k_consts<<<1, 32>>>();
    k_kde<<<ELF / 2, 64>>>(data_len);
    k_pair<<<L * F, 512>>>();
    k_out<<<1, 256>>>(out);
}

// round 8
// speedup vs baseline: 1.4885x; 1.1722x over previous
#include <cuda_runtime.h>
#include <math_constants.h>
#include <math.h>

#define E 4
#define L 8
#define S 512
#define F 32
#define SAMPLE 512
#define ELF (E * L * F)      /* 1024 */

typedef unsigned long long ull;

// ---------------- scratch (no allocations allowed) ----------------
__device__ float g_projT[ELF * S];            // [e][l][g][s]  raw proj (pre-std-scale)
__device__ float g_red[ELF * SAMPLE];         // red = ksum/len per (row, grid point)
__device__ float g_stdpart[E * L];
__device__ float g_bmin[256], g_bmax[256];
__device__ float g_c[8];                      // 0:uscale 1:qleft 2:qstep 3:scale_out
__device__ float g_store[6 * L * F];          // per-pair summed |diff|

__device__ __forceinline__ float ex2(float x) {
    float y; asm("ex2.approx.ftz.f32 %0, %1;" : "=f"(y) : "f"(x)); return y;
}
// f32x2 packed helpers (Blackwell packed fp32 pipe)
__device__ __forceinline__ ull pk2(float a, float b) {
    ull r; asm("mov.b64 %0, {%1, %2};" : "=l"(r) : "f"(a), "f"(b)); return r;
}
__device__ __forceinline__ void upk2(ull v, float& a, float& b) {
    asm("mov.b64 {%0, %1}, %2;" : "=f"(a), "=f"(b) : "l"(v));
}
__device__ __forceinline__ ull mul2(ull a, ull b) {
    ull r; asm("mul.rn.f32x2 %0, %1, %2;" : "=l"(r) : "l"(a), "l"(b)); return r;
}
__device__ __forceinline__ ull add2(ull a, ull b) {
    ull r; asm("add.rn.f32x2 %0, %1, %2;" : "=l"(r) : "l"(a), "l"(b)); return r;
}
__device__ __forceinline__ ull fma2(ull a, ull b, ull c) {
    ull r; asm("fma.rn.f32x2 %0, %1, %2, %3;" : "=l"(r) : "l"(a), "l"(b), "l"(c)); return r;
}

// ---------------- K1: per-(e,l,f) std (ddof=1), partial sums ----------------
__global__ void k_std(const float* __restrict__ matrix) {
    __shared__ float ssum[256], ssq[256];
    int b = blockIdx.x;                 // e*L + l
    int tid = threadIdx.x;
    int f = tid & 31, sg = tid >> 5;    // 32 f x 8 s-groups
    const float* base = matrix + (size_t)b * S * F;
    float s1 = 0.f, s2 = 0.f;
    for (int s = sg; s < S; s += 8) {
        float x = base[s * F + f];
        s1 += x; s2 += x * x;
    }
    ssum[tid] = s1; ssq[tid] = s2;
    __syncthreads();
    for (int st = 128; st >= 32; st >>= 1) {
        if (tid < st) { ssum[tid] += ssum[tid + st]; ssq[tid] += ssq[tid + st]; }
        __syncthreads();
    }
    if (tid < 32) {
        float sum = ssum[tid], sq = ssq[tid];
        float mean = sum / (float)S;
        float var = (sq - sum * mean) / (float)(S - 1);
        float sd = sqrtf(fmaxf(var, 0.f));
        #pragma unroll
        for (int o = 16; o; o >>= 1) sd += __shfl_down_sync(0xffffffffu, sd, o);
        if (tid == 0) g_stdpart[b] = sd;
    }
}

// ---------------- K2: proj = matrix @ params (raw), transposed store + min/max ----------------
__global__ void __launch_bounds__(256) k_proj(const float* __restrict__ matrix,
                                              const float* __restrict__ params) {
    __shared__ float sp[F * F];
    __shared__ float mt[64 * F];
    __shared__ float rmin[256], rmax[256];
    int b = blockIdx.x;                 // el*8 + stile
    int stile = b & 7;
    int el = b >> 3;
    int tid = threadIdx.x;
    for (int k = tid; k < F * F; k += 256) sp[k] = params[k];
    const float* mbase = matrix + ((size_t)el * S + (size_t)stile * 64) * F;
    for (int k = tid; k < 64 * F; k += 256) mt[k] = mbase[k];
    __syncthreads();
    float mn = CUDART_INF_F, mx = -CUDART_INF_F;
    int g = tid & 31;
    int sl0 = tid >> 5;
    #pragma unroll
    for (int k = 0; k < 8; k++) {
        int sl = sl0 + k * 8;
        float acc = 0.f;
        #pragma unroll
        for (int f = 0; f < F; f++)
            acc += mt[sl * F + f] * sp[f * F + g];
        g_projT[((size_t)el * F + g) * S + (size_t)stile * 64 + sl] = acc;
        mn = fminf(mn, acc); mx = fmaxf(mx, acc);
    }
    rmin[tid] = mn; rmax[tid] = mx;
    __syncthreads();
    for (int st = 128; st; st >>= 1) {
        if (tid < st) {
            rmin[tid] = fminf(rmin[tid], rmin[tid + st]);
            rmax[tid] = fmaxf(rmax[tid], rmax[tid + st]);
        }
        __syncthreads();
    }
    if (tid == 0) { g_bmin[b] = rmin[0]; g_bmax[b] = rmax[0]; }
}

// ---------------- K3: finalize scalars ----------------
__global__ void k_consts() {
    int t = threadIdx.x;   // 32 threads
    float sd = (t < E * L) ? g_stdpart[t] : 0.f;
    #pragma unroll
    for (int o = 16; o; o >>= 1) sd += __shfl_down_sync(0xffffffffu, sd, o);
    sd = __shfl_sync(0xffffffffu, sd, 0);
    float mn = CUDART_INF_F, mx = -CUDART_INF_F;
    for (int i = t; i < 256; i += 32) {
        mn = fminf(mn, g_bmin[i]); mx = fmaxf(mx, g_bmax[i]);
    }
    #pragma unroll
    for (int o = 16; o; o >>= 1) {
        mn = fminf(mn, __shfl_down_sync(0xffffffffu, mn, o));
        mx = fmaxf(mx, __shfl_down_sync(0xffffffffu, mx, o));
    }
    if (t == 0) {
        float stdv = sd / (float)ELF;
        // mean(std(matrix/stdv)) == stdv/stdv == 1 exactly (positive homogeneity)
        float bw = 1.06f * powf((float)S, -0.2f);
        float left = mn / stdv, right = mx / stdv;
        float range = right - left;
        float delta = range / (float)SAMPLE;
        float gstep = range / (float)(SAMPLE - 1);
        float inv2bw2 = 0.5f / (bw * bw);
        float coef = inv2bw2 * 1.4426950408889634f;  // exp(-a x^2) = 2^(-(x*sa)^2)
        float sa = sqrtf(coef);
        g_c[0] = sa / stdv;      // uscale
        g_c[1] = left * sa;      // qleft (scaled)
        g_c[2] = gstep * sa;     // qstep h (scaled)
        float divisor = sqrtf(2.f * CUDART_PI_F) * bw;
        g_c[3] = delta / (2.f * divisor);   // final per-pair scale
    }
}

// ---------------- K4: hot KDE — factored geometric recurrence (EXACT) ----------------
// K(u,p) = 2^{-(t0 - dp h)^2} = c * g^dp * W_dp,  c=2^{-t0^2}, g=2^{2 t0 h}, W_dp=2^{-(dp h)^2}.
// W_dp is sample-independent -> per sample only 2 EX2s; per grid point ~1 packed op.
// Masked-tail identity: (ksum - corr)/len == sum_{s<len} K/len -> only sum s<len.
// 4 warps per row, each sums a quarter of the samples; partials combined via smem.
__global__ void __launch_bounds__(128) k_kde(const int* __restrict__ data_len) {
    __shared__ float su[S];
    __shared__ float part[4][SAMPLE];
    int elf = blockIdx.x;                // one (e,l,f) row per block
    int el = elf >> 5;
    int tid = threadIdx.x;
    int warp = tid >> 5, lane = tid & 31;
    int len = data_len[el];
    float uscale = g_c[0], qleft = g_c[1], h = g_c[2];
    const float* src = g_projT + (size_t)elf * S;
    for (int s = tid; s < len; s += 128) su[s] = src[s] * uscale;
    __syncthreads();

    int quarter = (len + 3) >> 2;
    int sBeg = warp * quarter;
    int sEnd = min(sBeg + quarter, len);

    float twoh = 2.0f * h;
    float qb = qleft + (float)(lane << 4) * h;   // chunk base: 16 contiguous points per lane
    float m2hqb = -twoh * qb;
    ull a0, a1, a2, a3, a4, a5, a6, a7;
    a0 = a1 = a2 = a3 = a4 = a5 = a6 = a7 = pk2(0.f, 0.f);

    #pragma unroll 2
    for (int s = sBeg; s < sEnd; s++) {
        float u = su[s];
        float t0 = u - qb;
        float c = ex2(__fmul_rn(t0, -t0));
        float g = ex2(fmaf(u, twoh, m2hqb));
        float g2 = g * g;
        float g4 = g2 * g2;
        float g8 = g4 * g4;
        ull gg = pk2(g2, g2);
        ull G8 = pk2(g8, g8);
        ull tA = pk2(c, c * g);                  // points (0,1)
        a4 = fma2(tA, G8, a4); a0 = add2(a0, tA); tA = mul2(tA, gg);
        a5 = fma2(tA, G8, a5); a1 = add2(a1, tA); tA = mul2(tA, gg);
        a6 = fma2(tA, G8, a6); a2 = add2(a2, tA); tA = mul2(tA, gg);
        a7 = fma2(tA, G8, a7); a3 = add2(a3, tA);
    }

    float* pw = part[warp] + (lane << 4);
    upk2(a0, pw[0],  pw[1]);   upk2(a1, pw[2],  pw[3]);
    upk2(a2, pw[4],  pw[5]);   upk2(a3, pw[6],  pw[7]);
    upk2(a4, pw[8],  pw[9]);   upk2(a5, pw[10], pw[11]);
    upk2(a6, pw[12], pw[13]);  upk2(a7, pw[14], pw[15]);
    __syncthreads();

    // combine 4 warp-partials, apply W_dp and 1/len, write 4 points per thread
    float invlen = 1.0f / (float)len;
    int pt0 = tid << 2;
    float tmp[4];
    #pragma unroll
    for (int i = 0; i < 4; i++) {
        int pt = pt0 + i;
        float ssum = part[0][pt] + part[1][pt] + part[2][pt] + part[3][pt];
        float dh = (float)(pt & 15) * h;
        tmp[i] = ssum * ex2(__fmul_rn(dh, -dh)) * invlen;
    }
    *(float4*)(g_red + (size_t)elf * SAMPLE + pt0) =
        make_float4(tmp[0], tmp[1], tmp[2], tmp[3]);
}

// ---------------- K5: pairwise |diff| sums over grid (no division, 1 pt/thread) ----------------
__global__ void __launch_bounds__(512) k_pair() {
    __shared__ float sred[6][512];
    int b = blockIdx.x;                 // l*F + f
    int tid = threadIdx.x;              // grid point
    float r[E];
    #pragma unroll
    for (int e = 0; e < E; e++)
        r[e] = g_red[((size_t)(e * 256 + b)) * SAMPLE + tid];
    float local[6];
    int p = 0;
    #pragma unroll
    for (int i = 0; i < E; i++)
        #pragma unroll
        for (int j = i + 1; j < E; j++)
            local[p++] = fabsf(r[i] - r[j]);
    #pragma unroll
    for (p = 0; p < 6; p++) sred[p][tid] = local[p];
    __syncthreads();
    for (int st = 256; st; st >>= 1) {
        if (tid < st)
            #pragma unroll
            for (int q = 0; q < 6; q++) sred[q][tid] += sred[q][tid + st];
        __syncthreads();
    }
    if (tid < 6) g_store[tid * (L * F) + b] = sred[tid][0];
}

// ---------------- K6: maxima over pairs + scalars -> output ----------------
// pair order (i<j): 0:(0,1) 1:(0,2) 2:(0,3) 3:(1,2) 4:(1,3) 5:(2,3); train = {0,1,3}
__global__ void k_out(float* __restrict__ out) {
    __shared__ float str[256], ste[256];
    int tid = threadIdx.x;              // 256 = L*F
    float sc = g_c[3];
    float s0 = g_store[0 * 256 + tid], s1 = g_store[1 * 256 + tid], s2 = g_store[2 * 256 + tid];
    float s3 = g_store[3 * 256 + tid], s4 = g_store[4 * 256 + tid], s5 = g_store[5 * 256 + tid];
    float te = fmaxf(fmaxf(fmaxf(s0, s1), fmaxf(s2, s3)), fmaxf(s4, s5)) * sc;
    float tr = fmaxf(fmaxf(s0, s1), s3) * sc;
    out[tid] = tr;          // train_results (L,F)
    out[256 + tid] = te;    // test_results  (L,F)
    str[tid] = tr; ste[tid] = te;
    __syncthreads();
    if (tid < 32) {
        float mtr = -CUDART_INF_F, mte = -CUDART_INF_F;
        #pragma unroll
        for (int l = 0; l < L; l++) {
            mtr = fmaxf(mtr, str[l * 32 + tid]);
            mte = fmaxf(mte, ste[l * 32 + tid]);
        }
        #pragma unroll
        for (int o = 16; o; o >>= 1) {
            mtr += __shfl_down_sync(0xffffffffu, mtr, o);
            mte += __shfl_down_sync(0xffffffffu, mte, o);
        }
        if (tid == 0) { out[512] = mtr / 32.f; out[513] = mte / 32.f; }
    }
}

extern "C" void kernel_launch(void* const* d_in, const int* in_sizes, int n_in,
                              void* d_out, int out_size) {
    const float* matrix   = (const float*)d_in[0];   // (E,L,S,F) f32
    const float* params   = (const float*)d_in[1];   // (F,F) f32
    const int*   data_len = (const int*)d_in[2];     // (E,L) i32
    float* out = (float*)d_out;                      // 514 f32

    k_std<<<E * L, 256>>>(matrix);
    k_proj<<<256, 256>>>(matrix, params);
    k_consts<<<1, 32>>>();
    k_kde<<<ELF, 128>>>(data_len);
    k_pair<<<L * F, 512>>>();
    k_out<<<1, 256>>>(out);
}

// round 9
// speedup vs baseline: 1.6368x; 1.0996x over previous
#include <cuda_runtime.h>
#include <math_constants.h>
#include <math.h>

#define E 4
#define L 8
#define S 512
#define F 32
#define SAMPLE 512
#define ELF (E * L * F)      /* 1024 */

typedef unsigned long long ull;

// ---------------- scratch (no allocations allowed) ----------------
__device__ float g_projT[ELF * S];            // [e][l][g][s]  raw proj (pre-std-scale)
__device__ float g_red[ELF * SAMPLE];         // red = ksum/len per (row, grid point)
__device__ float g_sp1[256 * F];              // per-(el,stile,f) partial sum
__device__ float g_sp2[256 * F];              // per-(el,stile,f) partial sumsq
__device__ float g_bmin[256], g_bmax[256];
__device__ float g_c[8];                      // 0:uscale 1:qleft 2:qstep 3:scale_out
__device__ float g_store[6 * L * F];          // per-pair summed |diff|

__device__ __forceinline__ float ex2(float x) {
    float y; asm("ex2.approx.ftz.f32 %0, %1;" : "=f"(y) : "f"(x)); return y;
}
// f32x2 packed helpers (Blackwell packed fp32 pipe)
__device__ __forceinline__ ull pk2(float a, float b) {
    ull r; asm("mov.b64 %0, {%1, %2};" : "=l"(r) : "f"(a), "f"(b)); return r;
}
__device__ __forceinline__ void upk2(ull v, float& a, float& b) {
    asm("mov.b64 {%0, %1}, %2;" : "=f"(a), "=f"(b) : "l"(v));
}
__device__ __forceinline__ ull mul2(ull a, ull b) {
    ull r; asm("mul.rn.f32x2 %0, %1, %2;" : "=l"(r) : "l"(a), "l"(b)); return r;
}
__device__ __forceinline__ ull add2(ull a, ull b) {
    ull r; asm("add.rn.f32x2 %0, %1, %2;" : "=l"(r) : "l"(a), "l"(b)); return r;
}
__device__ __forceinline__ ull fma2(ull a, ull b, ull c) {
    ull r; asm("fma.rn.f32x2 %0, %1, %2, %3;" : "=l"(r) : "l"(a), "l"(b), "l"(c)); return r;
}

// ---------------- K1: proj = matrix @ params + std partials + min/max (fused) ----------------
__global__ void __launch_bounds__(256) k_proj(const float* __restrict__ matrix,
                                              const float* __restrict__ params) {
    __shared__ float sp[F * F];
    __shared__ float mt[64 * F];
    __shared__ float rmin[256], rmax[256];
    __shared__ float ssum[256], ssq[256];
    int b = blockIdx.x;                 // el*8 + stile
    int stile = b & 7;
    int el = b >> 3;
    int tid = threadIdx.x;
    for (int k = tid; k < F * F; k += 256) sp[k] = params[k];
    const float* mbase = matrix + ((size_t)el * S + (size_t)stile * 64) * F;
    for (int k = tid; k < 64 * F; k += 256) mt[k] = mbase[k];
    __syncthreads();

    // std partials: f = tid&31, rowgroup = tid>>5 (8 groups over 64 rows)
    {
        int f2 = tid & 31, rg = tid >> 5;
        float s1 = 0.f, s2 = 0.f;
        #pragma unroll
        for (int r = rg; r < 64; r += 8) {
            float x = mt[r * F + f2];
            s1 += x; s2 += x * x;
        }
        ssum[tid] = s1; ssq[tid] = s2;
    }

    // projection + min/max
    float mn = CUDART_INF_F, mx = -CUDART_INF_F;
    int g = tid & 31;
    int sl0 = tid >> 5;
    #pragma unroll
    for (int k = 0; k < 8; k++) {
        int sl = sl0 + k * 8;
        float acc = 0.f;
        #pragma unroll
        for (int f = 0; f < F; f++)
            acc += mt[sl * F + f] * sp[f * F + g];
        g_projT[((size_t)el * F + g) * S + (size_t)stile * 64 + sl] = acc;
        mn = fminf(mn, acc); mx = fmaxf(mx, acc);
    }
    rmin[tid] = mn; rmax[tid] = mx;
    __syncthreads();
    for (int st = 128; st; st >>= 1) {
        if (tid < st) {
            rmin[tid] = fminf(rmin[tid], rmin[tid + st]);
            rmax[tid] = fmaxf(rmax[tid], rmax[tid + st]);
            if (st >= 32) { ssum[tid] += ssum[tid + st]; ssq[tid] += ssq[tid + st]; }
        }
        __syncthreads();
    }
    if (tid < 32) { g_sp1[b * 32 + tid] = ssum[tid]; g_sp2[b * 32 + tid] = ssq[tid]; }
    if (tid == 0) { g_bmin[b] = rmin[0]; g_bmax[b] = rmax[0]; }
}

// ---------------- K2: finalize scalars ----------------
__global__ void k_consts() {
    __shared__ float ssd[256], smn[256], smx[256];
    int t = threadIdx.x;   // 256 threads
    float sdsum = 0.f;
    for (int c = t; c < ELF; c += 256) {
        int el = c >> 5, f = c & 31;
        float s1 = 0.f, s2 = 0.f;
        #pragma unroll
        for (int st = 0; st < 8; st++) {
            int idx = ((el * 8 + st) << 5) + f;
            s1 += g_sp1[idx]; s2 += g_sp2[idx];
        }
        float mean = s1 / (float)S;
        float var = (s2 - s1 * mean) / (float)(S - 1);
        sdsum += sqrtf(fmaxf(var, 0.f));
    }
    ssd[t] = sdsum; smn[t] = g_bmin[t]; smx[t] = g_bmax[t];
    __syncthreads();
    for (int st = 128; st; st >>= 1) {
        if (t < st) {
            ssd[t] += ssd[t + st];
            smn[t] = fminf(smn[t], smn[t + st]);
            smx[t] = fmaxf(smx[t], smx[t + st]);
        }
        __syncthreads();
    }
    if (t == 0) {
        float stdv = ssd[0] / (float)ELF;
        // mean(std(matrix/stdv)) == stdv/stdv == 1 exactly (positive homogeneity)
        float bw = 1.06f * powf((float)S, -0.2f);
        float left = smn[0] / stdv, right = smx[0] / stdv;
        float range = right - left;
        float delta = range / (float)SAMPLE;
        float gstep = range / (float)(SAMPLE - 1);
        float inv2bw2 = 0.5f / (bw * bw);
        float coef = inv2bw2 * 1.4426950408889634f;  // exp(-a x^2) = 2^(-(x*sa)^2)
        float sa = sqrtf(coef);
        g_c[0] = sa / stdv;      // uscale
        g_c[1] = left * sa;      // qleft (scaled)
        g_c[2] = gstep * sa;     // qstep h (scaled)
        float divisor = sqrtf(2.f * CUDART_PI_F) * bw;
        g_c[3] = delta / (2.f * divisor);   // final per-pair scale
    }
}

// ---------------- K3: hot KDE — factored geometric recurrence (EXACT) ----------------
// K(u,p) = 2^{-(t0 - dp h)^2} = c * g^dp * W_dp,  c=2^{-t0^2}, g=2^{2 t0 h}, W_dp=2^{-(dp h)^2}.
// W_dp is sample-independent -> per sample only 2 EX2s; per grid point ~1 packed op.
// Masked-tail identity: (ksum - corr)/len == sum_{s<len} K/len -> only sum s<len.
// 8 warps per row; each sums 1/8 of the samples; partials combined via smem (fixed order).
__global__ void __launch_bounds__(256, 6) k_kde(const int* __restrict__ data_len) {
    __shared__ float su[S];
    __shared__ float part[8][SAMPLE];
    int elf = blockIdx.x;                // one (e,l,f) row per block
    int el = elf >> 5;
    int tid = threadIdx.x;
    int warp = tid >> 5, lane = tid & 31;
    int len = data_len[el];
    float uscale = g_c[0], qleft = g_c[1], h = g_c[2];
    const float* src = g_projT + (size_t)elf * S;
    for (int s = tid; s < len; s += 256) su[s] = src[s] * uscale;
    __syncthreads();

    int eighth = (len + 7) >> 3;
    int sBeg = warp * eighth;
    int sEnd = min(sBeg + eighth, len);

    float twoh = 2.0f * h;
    float qb = qleft + (float)(lane << 4) * h;   // chunk base: 16 contiguous points per lane
    float m2hqb = -twoh * qb;
    ull a0, a1, a2, a3, a4, a5, a6, a7;
    a0 = a1 = a2 = a3 = a4 = a5 = a6 = a7 = pk2(0.f, 0.f);

    #pragma unroll 2
    for (int s = sBeg; s < sEnd; s++) {
        float u = su[s];
        float t0 = u - qb;
        float c = ex2(__fmul_rn(t0, -t0));
        float g = ex2(fmaf(u, twoh, m2hqb));
        float g2 = g * g;
        float g4 = g2 * g2;
        float g8 = g4 * g4;
        ull gg = pk2(g2, g2);
        ull G8 = pk2(g8, g8);
        ull tA = pk2(c, c * g);                  // points (0,1)
        a4 = fma2(tA, G8, a4); a0 = add2(a0, tA); tA = mul2(tA, gg);
        a5 = fma2(tA, G8, a5); a1 = add2(a1, tA); tA = mul2(tA, gg);
        a6 = fma2(tA, G8, a6); a2 = add2(a2, tA); tA = mul2(tA, gg);
        a7 = fma2(tA, G8, a7); a3 = add2(a3, tA);
    }

    float* pw = part[warp] + (lane << 4);
    upk2(a0, pw[0],  pw[1]);   upk2(a1, pw[2],  pw[3]);
    upk2(a2, pw[4],  pw[5]);   upk2(a3, pw[6],  pw[7]);
    upk2(a4, pw[8],  pw[9]);   upk2(a5, pw[10], pw[11]);
    upk2(a6, pw[12], pw[13]);  upk2(a7, pw[14], pw[15]);
    __syncthreads();

    // combine 8 warp-partials, apply W_dp and 1/len, write 2 points per thread
    float invlen = 1.0f / (float)len;
    int pt0 = tid << 1;
    float tmp[2];
    #pragma unroll
    for (int i = 0; i < 2; i++) {
        int pt = pt0 + i;
        float ssumv = ((part[0][pt] + part[1][pt]) + (part[2][pt] + part[3][pt]))
                    + ((part[4][pt] + part[5][pt]) + (part[6][pt] + part[7][pt]));
        float dh = (float)(pt & 15) * h;
        tmp[i] = ssumv * ex2(__fmul_rn(dh, -dh)) * invlen;
    }
    *(float2*)(g_red + (size_t)elf * SAMPLE + pt0) = make_float2(tmp[0], tmp[1]);
}

// ---------------- K4: pairwise |diff| sums over grid (1 pt/thread) ----------------
__global__ void __launch_bounds__(512) k_pair() {
    __shared__ float sred[6][512];
    int b = blockIdx.x;                 // l*F + f
    int tid = threadIdx.x;              // grid point
    float r[E];
    #pragma unroll
    for (int e = 0; e < E; e++)
        r[e] = g_red[((size_t)(e * 256 + b)) * SAMPLE + tid];
    float local[6];
    int p = 0;
    #pragma unroll
    for (int i = 0; i < E; i++)
        #pragma unroll
        for (int j = i + 1; j < E; j++)
            local[p++] = fabsf(r[i] - r[j]);
    #pragma unroll
    for (p = 0; p < 6; p++) sred[p][tid] = local[p];
    __syncthreads();
    for (int st = 256; st; st >>= 1) {
        if (tid < st)
            #pragma unroll
            for (int q = 0; q < 6; q++) sred[q][tid] += sred[q][tid + st];
        __syncthreads();
    }
    if (tid < 6) g_store[tid * (L * F) + b] = sred[tid][0];
}

// ---------------- K5: maxima over pairs + scalars -> output ----------------
// pair order (i<j): 0:(0,1) 1:(0,2) 2:(0,3) 3:(1,2) 4:(1,3) 5:(2,3); train = {0,1,3}
__global__ void k_out(float* __restrict__ out) {
    __shared__ float str[256], ste[256];
    int tid = threadIdx.x;              // 256 = L*F
    float sc = g_c[3];
    float s0 = g_store[0 * 256 + tid], s1 = g_store[1 * 256 + tid], s2 = g_store[2 * 256 + tid];
    float s3 = g_store[3 * 256 + tid], s4 = g_store[4 * 256 + tid], s5 = g_store[5 * 256 + tid];
    float te = fmaxf(fmaxf(fmaxf(s0, s1), fmaxf(s2, s3)), fmaxf(s4, s5)) * sc;
    float tr = fmaxf(fmaxf(s0, s1), s3) * sc;
    out[tid] = tr;          // train_results (L,F)
    out[256 + tid] = te;    // test_results  (L,F)
    str[tid] = tr; ste[tid] = te;
    __syncthreads();
    if (tid < 32) {
        float mtr = -CUDART_INF_F, mte = -CUDART_INF_F;
        #pragma unroll
        for (int l = 0; l < L; l++) {
            mtr = fmaxf(mtr, str[l * 32 + tid]);
            mte = fmaxf(mte, ste[l * 32 + tid]);
        }
        #pragma unroll
        for (int o = 16; o; o >>= 1) {
            mtr += __shfl_down_sync(0xffffffffu, mtr, o);
            mte += __shfl_down_sync(0xffffffffu, mte, o);
        }
        if (tid == 0) { out[512] = mtr / 32.f; out[513] = mte / 32.f; }
    }
}

extern "C" void kernel_launch(void* const* d_in, const int* in_sizes, int n_in,
                              void* d_out, int out_size) {
    const float* matrix   = (const float*)d_in[0];   // (E,L,S,F) f32
    const float* params   = (const float*)d_in[1];   // (F,F) f32
    const int*   data_len = (const int*)d_in[2];     // (E,L) i32
    float* out = (float*)d_out;                      // 514 f32

    k_proj<<<256, 256>>>(matrix, params);
    k_consts<<<1, 256>>>();
    k_kde<<<ELF, 256>>>(data_len);
    k_pair<<<L * F, 512>>>();
    k_out<<<1, 256>>>(out);
}